// round 6
// baseline (speedup 1.0000x reference)
#include <cuda_runtime.h>
#include <cuda_fp16.h>
#include <cstdint>

#define HH 64
#define WW 64
#define PP 4096          // HH*WW
#define CC 21
#define CPAD 24
#define NB 2
#define KS 71
#define KR 35
#define SPLITS 8
#define KRANGE (PP / SPLITS)   // 512
#define BM 128

// ---------------- scratch (static device globals; no allocation) ----------------
__device__ __align__(16) __half  d_Kh[(size_t)NB * PP * PP];    // 64 MiB K hi
__device__ __align__(16) __half  d_Kl[(size_t)NB * PP * PP];    // 64 MiB K lo (residual)
__device__ __align__(16) float   d_feats[NB * PP * 5];
__device__ __align__(16) float   d_U[NB * CC * PP];
__device__ __align__(16) float   d_q[NB * CC * PP];
__device__ __align__(16) __half  d_Vh[(size_t)NB * PP * CPAD];  // q probs fp16 hi, padded
__device__ __align__(16) __half  d_Vl[(size_t)NB * PP * CPAD];  // q probs fp16 lo
__device__ __align__(16) float   d_qbfp[(size_t)SPLITS * NB * CC * PP]; // split-K partials
__device__ __align__(16) float   d_tmp[NB * CC * PP];           // vertical conv result
__device__ __align__(16) float   d_comb[NB * CC * PP];          // 4*qbf + 2*qsf
__device__ float                 d_g1d[KS];

__device__ __forceinline__ void split_half(float v, __half& hi, __half& lo) {
    hi = __float2half(v);
    lo = __float2half(v - __half2float(hi));
}

// ---------------- prep: features ----------------
__global__ void feats_kernel(const float* __restrict__ ref, const float* __restrict__ kstd) {
    int idx = blockIdx.x * blockDim.x + threadIdx.x;
    if (idx >= NB * PP) return;
    int n = idx / PP, p = idx % PP;
    int y = p / WW, x = p % WW;
    const float* r = ref + (size_t)n * 3 * PP + p;
    d_feats[idx * 5 + 0] = (float)y / kstd[0];
    d_feats[idx * 5 + 1] = (float)x / kstd[1];
    d_feats[idx * 5 + 2] = r[0]        / kstd[2];
    d_feats[idx * 5 + 3] = r[PP]       / kstd[3];
    d_feats[idx * 5 + 4] = r[2 * PP]   / kstd[4];
}

// ---------------- prep: 1-D separable Gaussian from gk ----------------
__global__ void g1d_kernel(const float* __restrict__ gk) {
    int i = threadIdx.x;
    if (i < KS) {
        float center = gk[KR * KS + KR];
        d_g1d[i] = gk[i * KS + KR] * rsqrtf(center);
    }
}

// ---------------- prep: U = log(clip(unary)), q = softmax_C(U) ----------------
__global__ void init_kernel(const float* __restrict__ unary) {
    int idx = blockIdx.x * blockDim.x + threadIdx.x;
    if (idx >= NB * PP) return;
    int n = idx / PP, p = idx % PP;
    const float* u = unary + (size_t)n * CC * PP + p;
    float lg[CC];
    float m = -1e30f;
    #pragma unroll
    for (int c = 0; c < CC; ++c) {
        float v = u[(size_t)c * PP];
        v = fminf(fmaxf(v, 1e-5f), 1.0f);
        v = logf(v);
        lg[c] = v;
        m = fmaxf(m, v);
        d_U[((size_t)n * CC + c) * PP + p] = v;
    }
    float s = 0.f;
    #pragma unroll
    for (int c = 0; c < CC; ++c) { float e = expf(lg[c] - m); lg[c] = e; s += e; }
    float inv = 1.f / s;
    __half* vh = d_Vh + ((size_t)n * PP + p) * CPAD;
    __half* vl = d_Vl + ((size_t)n * PP + p) * CPAD;
    #pragma unroll
    for (int c = 0; c < CC; ++c) {
        float qv = lg[c] * inv;
        d_q[((size_t)n * CC + c) * PP + p] = qv;
        split_half(qv, vh[c], vl[c]);
    }
    #pragma unroll
    for (int c = CC; c < CPAD; ++c) { vh[c] = __float2half(0.f); vl[c] = __float2half(0.f); }
}

// ---------------- build K (fp16 hi+lo), 32x128 tiles, half2 stores ----------------
__global__ __launch_bounds__(256) void buildK_kernel() {
    __shared__ float fp[32][5];    // p rows
    __shared__ float fq[128][5];   // q cols
    int n  = blockIdx.z;
    int p0 = blockIdx.y * 32;
    int q0 = blockIdx.x * 128;
    int tx = threadIdx.x;          // 0..63 -> 2 q cols each
    int ty = threadIdx.y;          // 0..3
    int tid = ty * 64 + tx;

    for (int i = tid; i < 160; i += 256)
        (&fp[0][0])[i] = d_feats[((size_t)n * PP + p0) * 5 + i];
    for (int i = tid; i < 640; i += 256)
        (&fq[0][0])[i] = d_feats[((size_t)n * PP + q0) * 5 + i];
    __syncthreads();

    int c0 = tx * 2;
    float a00 = fq[c0][0], a01 = fq[c0][1], a02 = fq[c0][2], a03 = fq[c0][3], a04 = fq[c0][4];
    float a10 = fq[c0+1][0], a11 = fq[c0+1][1], a12 = fq[c0+1][2], a13 = fq[c0+1][3], a14 = fq[c0+1][4];

    __half* Khb = d_Kh + (size_t)n * PP * PP;
    __half* Klb = d_Kl + (size_t)n * PP * PP;
    uint32_t off = (uint32_t)(p0 + ty) * PP + (uint32_t)(q0 + c0);

    #pragma unroll 8
    for (int r = ty; r < 32; r += 4, off += 4u * PP) {
        float b0 = fp[r][0], b1 = fp[r][1], b2 = fp[r][2], b3 = fp[r][3], b4 = fp[r][4];
        float x0 = b0 - a00, x1 = b1 - a01, x2 = b2 - a02, x3 = b3 - a03, x4 = b4 - a04;
        float d0 = x0*x0 + x1*x1 + x2*x2 + x3*x3 + x4*x4;
        float y0 = b0 - a10, y1 = b1 - a11, y2 = b2 - a12, y3 = b3 - a13, y4 = b4 - a14;
        float d1 = y0*y0 + y1*y1 + y2*y2 + y3*y3 + y4*y4;
        float k0 = __expf(-0.5f * d0);
        float k1 = __expf(-0.5f * d1);
        __half h0, l0, h1, l1;
        split_half(k0, h0, l0);
        split_half(k1, h1, l1);
        *(__half2*)(Khb + off) = __halves2half2(h0, h1);
        *(__half2*)(Klb + off) = __halves2half2(l0, l1);
    }
}

// ---- GEMM: qbf[c,p] = sum_q K[p,q]*V[q,c], compensated fp16, split-K ----
// B (whole K-slice of V, hi+lo) persists in smem; A fragments come straight
// from gmem via per-thread LDG.32 at mma fragment coordinates. No mainloop syncs.
__global__ __launch_bounds__(256) void gemm_kernel() {
    __shared__ __align__(16) __half Bsh[KRANGE][CPAD];   // 24576 B
    __shared__ __align__(16) __half Bsl[KRANGE][CPAD];   // 24576 B  (total 49152)

    int n   = blockIdx.z;
    int spl = blockIdx.y;
    int p0  = blockIdx.x * BM;
    int ks0 = spl * KRANGE;
    int tid = threadIdx.x;
    int warp = tid >> 5, lane = tid & 31;

    // load whole B slice once
    const float4* Vh4 = (const float4*)(d_Vh + ((size_t)n * PP + ks0) * CPAD);
    const float4* Vl4 = (const float4*)(d_Vl + ((size_t)n * PP + ks0) * CPAD);
    float4* Bh4 = (float4*)&Bsh[0][0];
    float4* Bl4 = (float4*)&Bsl[0][0];
    #pragma unroll
    for (int i = 0; i < (KRANGE * CPAD / 8) / 256; ++i) {
        Bh4[tid + i * 256] = Vh4[tid + i * 256];
        Bl4[tid + i * 256] = Vl4[tid + i * 256];
    }
    __syncthreads();

    int row = p0 + warp * 16 + (lane >> 2);
    const __half* Ah = d_Kh + (size_t)n * PP * PP + (size_t)row * PP + ks0 + 2 * (lane & 3);
    const __half* Al = d_Kl + (size_t)n * PP * PP + (size_t)row * PP + ks0 + 2 * (lane & 3);

    float acc[3][4];
    #pragma unroll
    for (int i = 0; i < 3; ++i)
        #pragma unroll
        for (int j = 0; j < 4; ++j) acc[i][j] = 0.f;

    #pragma unroll 4
    for (int k16 = 0; k16 < KRANGE / 16; ++k16) {
        int kof = k16 * 16;
        uint32_t ah0 = *(const uint32_t*)(Ah + kof);
        uint32_t ah1 = *(const uint32_t*)(Ah + 8 * PP + kof);
        uint32_t ah2 = *(const uint32_t*)(Ah + kof + 8);
        uint32_t ah3 = *(const uint32_t*)(Ah + 8 * PP + kof + 8);
        uint32_t al0 = *(const uint32_t*)(Al + kof);
        uint32_t al1 = *(const uint32_t*)(Al + 8 * PP + kof);
        uint32_t al2 = *(const uint32_t*)(Al + kof + 8);
        uint32_t al3 = *(const uint32_t*)(Al + 8 * PP + kof + 8);
        #pragma unroll
        for (int nt = 0; nt < 3; ++nt) {
            uint32_t bh0, bh1, bl0, bl1;
            uint32_t baddr_h = (uint32_t)__cvta_generic_to_shared(
                &Bsh[kof + (lane & 15)][nt * 8]);
            uint32_t baddr_l = (uint32_t)__cvta_generic_to_shared(
                &Bsl[kof + (lane & 15)][nt * 8]);
            asm volatile("ldmatrix.sync.aligned.m8n8.x2.trans.shared.b16 {%0,%1}, [%2];"
                         : "=r"(bh0), "=r"(bh1) : "r"(baddr_h));
            asm volatile("ldmatrix.sync.aligned.m8n8.x2.trans.shared.b16 {%0,%1}, [%2];"
                         : "=r"(bl0), "=r"(bl1) : "r"(baddr_l));
            asm volatile(
                "mma.sync.aligned.m16n8k16.row.col.f32.f16.f16.f32 "
                "{%0,%1,%2,%3}, {%4,%5,%6,%7}, {%8,%9}, {%0,%1,%2,%3};"
                : "+f"(acc[nt][0]), "+f"(acc[nt][1]), "+f"(acc[nt][2]), "+f"(acc[nt][3])
                : "r"(ah0), "r"(ah1), "r"(ah2), "r"(ah3), "r"(bh0), "r"(bh1));
            asm volatile(
                "mma.sync.aligned.m16n8k16.row.col.f32.f16.f16.f32 "
                "{%0,%1,%2,%3}, {%4,%5,%6,%7}, {%8,%9}, {%0,%1,%2,%3};"
                : "+f"(acc[nt][0]), "+f"(acc[nt][1]), "+f"(acc[nt][2]), "+f"(acc[nt][3])
                : "r"(ah0), "r"(ah1), "r"(ah2), "r"(ah3), "r"(bl0), "r"(bl1));
            asm volatile(
                "mma.sync.aligned.m16n8k16.row.col.f32.f16.f16.f32 "
                "{%0,%1,%2,%3}, {%4,%5,%6,%7}, {%8,%9}, {%0,%1,%2,%3};"
                : "+f"(acc[nt][0]), "+f"(acc[nt][1]), "+f"(acc[nt][2]), "+f"(acc[nt][3])
                : "r"(al0), "r"(al1), "r"(al2), "r"(al3), "r"(bh0), "r"(bh1));
        }
    }

    // epilogue: scatter partials
    float* qbf = d_qbfp + ((size_t)(spl * NB + n) * CC) * PP;
    int prow = p0 + warp * 16 + (lane >> 2);
    int cb = (lane & 3) * 2;
    #pragma unroll
    for (int nt = 0; nt < 3; ++nt)
        #pragma unroll
        for (int r = 0; r < 4; ++r) {
            int c = nt * 8 + cb + (r & 1);
            int p = prow + (r >> 1) * 8;
            if (c < CC) qbf[(size_t)c * PP + p] = acc[nt][r];
        }
}

// ---------------- vertical 1-D conv on q -> tmp ----------------
__global__ void vconv_kernel() {
    int idx = blockIdx.x * blockDim.x + threadIdx.x;
    if (idx >= NB * CC * PP) return;
    int x = idx & 63, y = (idx >> 6) & 63, nc = idx >> 12;
    const float* base = d_q + (size_t)nc * PP;
    int dlo = (35 - y) > 0 ? (35 - y) : 0;
    int dhi = (98 - y) < 70 ? (98 - y) : 70;
    float acc = 0.f;
    for (int d = dlo; d <= dhi; ++d)
        acc += d_g1d[d] * base[(y + d - KR) * WW + x];
    d_tmp[idx] = acc;
}

// ------- horizontal 1-D conv + merge split-K partials: comb = 4*qbf + 2*qsf -------
__global__ void hconv_kernel() {
    int idx = blockIdx.x * blockDim.x + threadIdx.x;
    if (idx >= NB * CC * PP) return;
    int x = idx & 63;
    int dlo = (35 - x) > 0 ? (35 - x) : 0;
    int dhi = (98 - x) < 70 ? (98 - x) : 70;
    float s = 0.f;
    for (int d = dlo; d <= dhi; ++d)
        s += d_g1d[d] * d_tmp[idx + d - KR];
    float qb = 0.f;
    const size_t SPL = (size_t)NB * CC * PP;
    #pragma unroll
    for (int sp = 0; sp < SPLITS; ++sp)
        qb += d_qbfp[sp * SPL + idx];
    d_comb[idx] = 4.0f * qb + 2.0f * s;
}

// ---------------- softmax update: q = softmax(U + comb) ----------------
__global__ __launch_bounds__(128) void update_kernel(float* __restrict__ outp, int write_out) {
    int idx = blockIdx.x * blockDim.x + threadIdx.x;
    if (idx >= NB * PP) return;
    int n = idx >> 12, p = idx & 4095;
    const float* Ub = d_U    + (size_t)n * CC * PP + p;
    const float* Cb = d_comb + (size_t)n * CC * PP + p;
    float lg[CC];
    float m = -1e30f;
    #pragma unroll
    for (int c = 0; c < CC; ++c) {
        float v = Ub[(size_t)c * PP] + Cb[(size_t)c * PP];
        lg[c] = v;
        m = fmaxf(m, v);
    }
    float ssum = 0.f;
    #pragma unroll
    for (int c = 0; c < CC; ++c) { float e = expf(lg[c] - m); lg[c] = e; ssum += e; }
    float inv = 1.f / ssum;
    __half* vh = d_Vh + ((size_t)n * PP + p) * CPAD;
    __half* vl = d_Vl + ((size_t)n * PP + p) * CPAD;
    #pragma unroll
    for (int c = 0; c < CC; ++c) {
        float qv = lg[c] * inv;
        size_t o = ((size_t)n * CC + c) * PP + p;
        d_q[o] = qv;
        split_half(qv, vh[c], vl[c]);
        if (write_out) outp[o] = qv;
    }
}

// ---------------- launch ----------------
extern "C" void kernel_launch(void* const* d_in, const int* in_sizes, int n_in,
                              void* d_out, int out_size) {
    const float* unary = (const float*)d_in[0];
    const float* ref   = (const float*)d_in[1];
    const float* gk    = (const float*)d_in[2];
    const float* kstd  = (const float*)d_in[3];
    float* out = (float*)d_out;

    feats_kernel<<<(NB * PP + 255) / 256, 256>>>(ref, kstd);
    g1d_kernel<<<1, 128>>>(gk);
    init_kernel<<<(NB * PP + 255) / 256, 256>>>(unary);
    buildK_kernel<<<dim3(PP / 128, PP / 32, NB), dim3(64, 4)>>>();

    for (int it = 0; it < 5; ++it) {
        vconv_kernel<<<(NB * CC * PP + 255) / 256, 256>>>();
        gemm_kernel<<<dim3(PP / BM, SPLITS, NB), 256>>>();
        hconv_kernel<<<(NB * CC * PP + 255) / 256, 256>>>();
        update_kernel<<<(NB * PP + 127) / 128, 128>>>(out, it == 4 ? 1 : 0);
    }
}

// round 7
// speedup vs baseline: 1.1703x; 1.1703x over previous
#include <cuda_runtime.h>
#include <cuda_fp16.h>
#include <cstdint>

#define HH 64
#define WW 64
#define PP 4096          // HH*WW
#define CC 21
#define CPAD 24
#define NB 2
#define KS 71
#define KR 35
#define SPLITS 4
#define KRANGE (PP / SPLITS)   // 1024
#define BM 64
#define KC 64
#define NCH (KRANGE / KC)      // 16
#define STAGE_BYTES (2*(BM*KC*2) + 2*(KC*CPAD*2))   // 22528

// ---------------- scratch (static device globals; no allocation) ----------------
// K stored TILED: [n][pb][qc][64*64] halves, 8KB per tile, segment-swizzled.
__device__ __align__(16) __half  d_Kth[(size_t)NB * PP * PP];
__device__ __align__(16) __half  d_Ktl[(size_t)NB * PP * PP];
__device__ __align__(16) float   d_feats[NB * PP * 5];
__device__ __align__(16) float   d_U[NB * CC * PP];
__device__ __align__(16) float   d_q[NB * CC * PP];
__device__ __align__(16) __half  d_Vh[(size_t)NB * PP * CPAD];
__device__ __align__(16) __half  d_Vl[(size_t)NB * PP * CPAD];
__device__ __align__(16) float   d_qbfp[(size_t)SPLITS * NB * CC * PP];
__device__ __align__(16) float   d_tmp[NB * CC * PP];
__device__ float                 d_g1d[KS];

// ---------------- async helpers ----------------
#define CP_BULK(dst_s, src_g, nbytes, mbar_s) \
    asm volatile("cp.async.bulk.shared::cta.global.mbarrier::complete_tx::bytes [%0], [%1], %2, [%3];" \
        :: "r"(dst_s), "l"(src_g), "r"(nbytes), "r"(mbar_s) : "memory")
#define MBAR_INIT(mbar_s, cnt) \
    asm volatile("mbarrier.init.shared.b64 [%0], %1;" :: "r"(mbar_s), "r"(cnt) : "memory")
#define MBAR_EXPECT_TX(mbar_s, tx) \
    asm volatile("mbarrier.arrive.expect_tx.shared.b64 _, [%0], %1;" :: "r"(mbar_s), "r"(tx) : "memory")
#define MBAR_ARRIVE(mbar_s) \
    asm volatile("mbarrier.arrive.shared.b64 _, [%0];" :: "r"(mbar_s) : "memory")
#define MBAR_WAIT(mbar_s, parity) do { \
    asm volatile( \
        "{\n\t.reg .pred P;\n\t" \
        "WAIT_%=:\n\t" \
        "mbarrier.try_wait.parity.acquire.cta.shared::cta.b64 P, [%0], %1, 0x989680;\n\t" \
        "@P bra.uni DONE_%=;\n\t" \
        "bra.uni WAIT_%=;\n\t" \
        "DONE_%=:\n\t}" \
        :: "r"(mbar_s), "r"(parity) : "memory"); \
} while (0)

__device__ __forceinline__ void split_half(float v, __half& hi, __half& lo) {
    hi = __float2half(v);
    lo = __float2half(v - __half2float(hi));
}

// ---------------- prep: features ----------------
__global__ void feats_kernel(const float* __restrict__ ref, const float* __restrict__ kstd) {
    int idx = blockIdx.x * blockDim.x + threadIdx.x;
    if (idx >= NB * PP) return;
    int n = idx / PP, p = idx % PP;
    int y = p / WW, x = p % WW;
    const float* r = ref + (size_t)n * 3 * PP + p;
    d_feats[idx * 5 + 0] = (float)y / kstd[0];
    d_feats[idx * 5 + 1] = (float)x / kstd[1];
    d_feats[idx * 5 + 2] = r[0]        / kstd[2];
    d_feats[idx * 5 + 3] = r[PP]       / kstd[3];
    d_feats[idx * 5 + 4] = r[2 * PP]   / kstd[4];
}

// ---------------- prep: 1-D separable Gaussian from gk ----------------
__global__ void g1d_kernel(const float* __restrict__ gk) {
    int i = threadIdx.x;
    if (i < KS) {
        float center = gk[KR * KS + KR];
        d_g1d[i] = gk[i * KS + KR] * rsqrtf(center);
    }
}

// ---------------- prep: U = log(clip(unary)), q = softmax_C(U) ----------------
__global__ void init_kernel(const float* __restrict__ unary) {
    int idx = blockIdx.x * blockDim.x + threadIdx.x;
    if (idx >= NB * PP) return;
    int n = idx / PP, p = idx % PP;
    const float* u = unary + (size_t)n * CC * PP + p;
    float lg[CC];
    float m = -1e30f;
    #pragma unroll
    for (int c = 0; c < CC; ++c) {
        float v = u[(size_t)c * PP];
        v = fminf(fmaxf(v, 1e-5f), 1.0f);
        v = logf(v);
        lg[c] = v;
        m = fmaxf(m, v);
        d_U[((size_t)n * CC + c) * PP + p] = v;
    }
    float s = 0.f;
    #pragma unroll
    for (int c = 0; c < CC; ++c) { float e = expf(lg[c] - m); lg[c] = e; s += e; }
    float inv = 1.f / s;
    __half* vh = d_Vh + ((size_t)n * PP + p) * CPAD;
    __half* vl = d_Vl + ((size_t)n * PP + p) * CPAD;
    #pragma unroll
    for (int c = 0; c < CC; ++c) {
        float qv = lg[c] * inv;
        d_q[((size_t)n * CC + c) * PP + p] = qv;
        split_half(qv, vh[c], vl[c]);
    }
    #pragma unroll
    for (int c = CC; c < CPAD; ++c) { vh[c] = __float2half(0.f); vl[c] = __float2half(0.f); }
}

// ---------------- build K (fp16 hi+lo), TILED+swizzled layout ----------------
// tile offset for (n,p,q): pb=p>>6, pr=p&63, qc=q>>6; inner = pr*64 + (seg^)*8 + q&7
__global__ __launch_bounds__(256) void buildK_kernel() {
    __shared__ float fp[32][5];    // p rows
    __shared__ float fq[128][5];   // q cols
    int n  = blockIdx.z;
    int p0 = blockIdx.y * 32;
    int q0 = blockIdx.x * 128;
    int tx = threadIdx.x;          // 0..63 -> 2 q cols each
    int ty = threadIdx.y;          // 0..3
    int tid = ty * 64 + tx;

    for (int i = tid; i < 160; i += 256)
        (&fp[0][0])[i] = d_feats[((size_t)n * PP + p0) * 5 + i];
    for (int i = tid; i < 640; i += 256)
        (&fq[0][0])[i] = d_feats[((size_t)n * PP + q0) * 5 + i];
    __syncthreads();

    int c0 = tx * 2;                       // 0..126
    int q  = q0 + c0;
    float a00 = fq[c0][0], a01 = fq[c0][1], a02 = fq[c0][2], a03 = fq[c0][3], a04 = fq[c0][4];
    float a10 = fq[c0+1][0], a11 = fq[c0+1][1], a12 = fq[c0+1][2], a13 = fq[c0+1][3], a14 = fq[c0+1][4];

    int pb = p0 >> 6;
    int qc = q >> 6;
    int qseg0 = (q >> 3) & 7;
    int qin   = q & 7;                      // even
    // tile base for (n, pb, qc)
    size_t tbase = ((((size_t)n * (PP/64) + pb) * (PP/64)) + qc) << 12;   // *4096
    __half* Khb = d_Kth;
    __half* Klb = d_Ktl;

    #pragma unroll 8
    for (int r = ty; r < 32; r += 4) {
        int pr = (p0 & 63) + r;             // row within tile (p0 multiple of 32)
        float b0 = fp[r][0], b1 = fp[r][1], b2 = fp[r][2], b3 = fp[r][3], b4 = fp[r][4];
        float x0 = b0 - a00, x1 = b1 - a01, x2 = b2 - a02, x3 = b3 - a03, x4 = b4 - a04;
        float d0 = x0*x0 + x1*x1 + x2*x2 + x3*x3 + x4*x4;
        float y0 = b0 - a10, y1 = b1 - a11, y2 = b2 - a12, y3 = b3 - a13, y4 = b4 - a14;
        float d1 = y0*y0 + y1*y1 + y2*y2 + y3*y3 + y4*y4;
        float k0 = __expf(-0.5f * d0);
        float k1 = __expf(-0.5f * d1);
        __half h0, l0, h1, l1;
        split_half(k0, h0, l0);
        split_half(k1, h1, l1);
        size_t off = tbase + (size_t)(pr << 6) + ((qseg0 ^ (pr & 7)) << 3) + qin;
        *(__half2*)(Khb + off) = __halves2half2(h0, h1);
        *(__half2*)(Klb + off) = __halves2half2(l0, l1);
    }
}

// ---- GEMM: qbf[c,p] = sum_q K[p,q]*V[q,c], compensated fp16, split-K ----
// A tiles arrive via single 8KB cp.async.bulk per stage (pre-swizzled tiled K).
// 2-stage mbarrier full/empty pipeline, no __syncthreads in mainloop.
__global__ __launch_bounds__(128) void gemm_kernel() {
    __shared__ __align__(16) __half Ash[2][BM][KC];      // 16384 B
    __shared__ __align__(16) __half Asl[2][BM][KC];      // 16384 B
    __shared__ __align__(16) __half Bsh[2][KC][CPAD];    // 6144 B
    __shared__ __align__(16) __half Bsl[2][KC][CPAD];    // 6144 B  (45056 total)
    __shared__ __align__(8) uint64_t mb_full[2];
    __shared__ __align__(8) uint64_t mb_empty[2];

    int n   = blockIdx.z;
    int spl = blockIdx.y;
    int pb  = blockIdx.x;            // 64-row block
    int p0  = pb * BM;
    int qc0 = spl * (KRANGE / 64);   // first 64-col tile of this split
    int tid = threadIdx.x;
    int warp = tid >> 5, lane = tid & 31;

    uint32_t full_s[2], empty_s[2];
    #pragma unroll
    for (int s = 0; s < 2; ++s) {
        full_s[s]  = (uint32_t)__cvta_generic_to_shared(&mb_full[s]);
        empty_s[s] = (uint32_t)__cvta_generic_to_shared(&mb_empty[s]);
    }
    if (tid == 0) {
        MBAR_INIT(full_s[0], 1);  MBAR_INIT(full_s[1], 1);
        MBAR_INIT(empty_s[0], 128); MBAR_INIT(empty_s[1], 128);
    }
    __syncthreads();

    const char* Ktile_h = (const char*)(d_Kth + (((((size_t)n * 64 + pb) * 64) + qc0) << 12));
    const char* Ktile_l = (const char*)(d_Ktl + (((((size_t)n * 64 + pb) * 64) + qc0) << 12));
    const char* Vh_g = (const char*)(d_Vh + ((size_t)n * PP + spl * KRANGE) * CPAD);
    const char* Vl_g = (const char*)(d_Vl + ((size_t)n * PP + spl * KRANGE) * CPAD);

    auto issue = [&](int ch) {
        int s = ch & 1;
        MBAR_EXPECT_TX(full_s[s], (uint32_t)STAGE_BYTES);
        CP_BULK((uint32_t)__cvta_generic_to_shared(&Ash[s][0][0]), Ktile_h + (size_t)ch * 8192, 8192u, full_s[s]);
        CP_BULK((uint32_t)__cvta_generic_to_shared(&Asl[s][0][0]), Ktile_l + (size_t)ch * 8192, 8192u, full_s[s]);
        CP_BULK((uint32_t)__cvta_generic_to_shared(&Bsh[s][0][0]), Vh_g + (size_t)ch * 3072, 3072u, full_s[s]);
        CP_BULK((uint32_t)__cvta_generic_to_shared(&Bsl[s][0][0]), Vl_g + (size_t)ch * 3072, 3072u, full_s[s]);
    };

    if (tid == 0) { issue(0); issue(1); }

    float acc[3][4];
    #pragma unroll
    for (int i = 0; i < 3; ++i)
        #pragma unroll
        for (int j = 0; j < 4; ++j) acc[i][j] = 0.f;

    int m0 = warp * 16;
    for (int ch = 0; ch < NCH; ++ch) {
        int s = ch & 1;
        MBAR_WAIT(full_s[s], (ch >> 1) & 1);

        #pragma unroll
        for (int kk = 0; kk < KC / 16; ++kk) {
            int arow = m0 + (lane & 15);
            int aseg = (kk * 2 + (lane >> 4)) ^ (arow & 7);
            uint32_t ah0, ah1, ah2, ah3, al0, al1, al2, al3;
            uint32_t aaddr_h = (uint32_t)__cvta_generic_to_shared(&Ash[s][arow][aseg * 8]);
            uint32_t aaddr_l = (uint32_t)__cvta_generic_to_shared(&Asl[s][arow][aseg * 8]);
            asm volatile("ldmatrix.sync.aligned.m8n8.x4.shared.b16 {%0,%1,%2,%3}, [%4];"
                         : "=r"(ah0), "=r"(ah1), "=r"(ah2), "=r"(ah3) : "r"(aaddr_h));
            asm volatile("ldmatrix.sync.aligned.m8n8.x4.shared.b16 {%0,%1,%2,%3}, [%4];"
                         : "=r"(al0), "=r"(al1), "=r"(al2), "=r"(al3) : "r"(aaddr_l));
            #pragma unroll
            for (int nt = 0; nt < 3; ++nt) {
                uint32_t bh0, bh1, bl0, bl1;
                uint32_t baddr_h = (uint32_t)__cvta_generic_to_shared(
                    &Bsh[s][kk * 16 + (lane & 15)][nt * 8]);
                uint32_t baddr_l = (uint32_t)__cvta_generic_to_shared(
                    &Bsl[s][kk * 16 + (lane & 15)][nt * 8]);
                asm volatile("ldmatrix.sync.aligned.m8n8.x2.trans.shared.b16 {%0,%1}, [%2];"
                             : "=r"(bh0), "=r"(bh1) : "r"(baddr_h));
                asm volatile("ldmatrix.sync.aligned.m8n8.x2.trans.shared.b16 {%0,%1}, [%2];"
                             : "=r"(bl0), "=r"(bl1) : "r"(baddr_l));
                asm volatile(
                    "mma.sync.aligned.m16n8k16.row.col.f32.f16.f16.f32 "
                    "{%0,%1,%2,%3}, {%4,%5,%6,%7}, {%8,%9}, {%0,%1,%2,%3};"
                    : "+f"(acc[nt][0]), "+f"(acc[nt][1]), "+f"(acc[nt][2]), "+f"(acc[nt][3])
                    : "r"(ah0), "r"(ah1), "r"(ah2), "r"(ah3), "r"(bh0), "r"(bh1));
                asm volatile(
                    "mma.sync.aligned.m16n8k16.row.col.f32.f16.f16.f32 "
                    "{%0,%1,%2,%3}, {%4,%5,%6,%7}, {%8,%9}, {%0,%1,%2,%3};"
                    : "+f"(acc[nt][0]), "+f"(acc[nt][1]), "+f"(acc[nt][2]), "+f"(acc[nt][3])
                    : "r"(ah0), "r"(ah1), "r"(ah2), "r"(ah3), "r"(bl0), "r"(bl1));
                asm volatile(
                    "mma.sync.aligned.m16n8k16.row.col.f32.f16.f16.f32 "
                    "{%0,%1,%2,%3}, {%4,%5,%6,%7}, {%8,%9}, {%0,%1,%2,%3};"
                    : "+f"(acc[nt][0]), "+f"(acc[nt][1]), "+f"(acc[nt][2]), "+f"(acc[nt][3])
                    : "r"(al0), "r"(al1), "r"(al2), "r"(al3), "r"(bh0), "r"(bh1));
            }
        }

        MBAR_ARRIVE(empty_s[s]);
        if (tid == 0 && ch + 2 < NCH) {
            MBAR_WAIT(empty_s[s], (ch >> 1) & 1);
            issue(ch + 2);
        }
    }

    // epilogue: scatter partials
    float* qbf = d_qbfp + ((size_t)(spl * NB + n) * CC) * PP;
    int prow = p0 + warp * 16 + (lane >> 2);
    int cb = (lane & 3) * 2;
    #pragma unroll
    for (int nt = 0; nt < 3; ++nt)
        #pragma unroll
        for (int r = 0; r < 4; ++r) {
            int c = nt * 8 + cb + (r & 1);
            int p = prow + (r >> 1) * 8;
            if (c < CC) qbf[(size_t)c * PP + p] = acc[nt][r];
        }
}

// ---------------- vertical 1-D conv on q -> tmp ----------------
__global__ void vconv_kernel() {
    int idx = blockIdx.x * blockDim.x + threadIdx.x;
    if (idx >= NB * CC * PP) return;
    int x = idx & 63, y = (idx >> 6) & 63, nc = idx >> 12;
    const float* base = d_q + (size_t)nc * PP;
    int dlo = (35 - y) > 0 ? (35 - y) : 0;
    int dhi = (98 - y) < 70 ? (98 - y) : 70;
    float acc = 0.f;
    for (int d = dlo; d <= dhi; ++d)
        acc += d_g1d[d] * base[(y + d - KR) * WW + x];
    d_tmp[idx] = acc;
}

// ---------------- horizontal conv + combine + softmax ----------------
__global__ __launch_bounds__(64) void hcombine_kernel(float* __restrict__ outp, int write_out) {
    __shared__ float row[CC][WW + 2 * KR];
    __shared__ float g[KS];
    int bn = blockIdx.x;
    int n = bn >> 6, y = bn & 63;
    int x = threadIdx.x;

    for (int i = x; i < KS; i += 64) g[i] = d_g1d[i];
    #pragma unroll
    for (int c = 0; c < CC; ++c) {
        row[c][KR + x] = d_tmp[((size_t)n * CC + c) * PP + y * WW + x];
        if (x < KR) { row[c][x] = 0.f; row[c][KR + WW + x] = 0.f; }
    }
    __syncthreads();

    const size_t SPL = (size_t)NB * CC * PP;
    const float* Ub = d_U    + (size_t)n * CC * PP + y * WW + x;
    const float* Qb = d_qbfp + (size_t)n * CC * PP + y * WW + x;
    float lg[CC];
    float m = -1e30f;
    #pragma unroll
    for (int c = 0; c < CC; ++c) {
        float s = 0.f;
        #pragma unroll 7
        for (int d = 0; d < KS; ++d) s += g[d] * row[c][x + d];
        float qb = Qb[(size_t)c * PP] + Qb[SPL + (size_t)c * PP]
                 + Qb[2 * SPL + (size_t)c * PP] + Qb[3 * SPL + (size_t)c * PP];
        float v = Ub[(size_t)c * PP] + 4.0f * qb + 2.0f * s;
        lg[c] = v;
        m = fmaxf(m, v);
    }
    float ssum = 0.f;
    #pragma unroll
    for (int c = 0; c < CC; ++c) { float e = expf(lg[c] - m); lg[c] = e; ssum += e; }
    float inv = 1.f / ssum;
    __half* vh = d_Vh + ((size_t)n * PP + y * WW + x) * CPAD;
    __half* vl = d_Vl + ((size_t)n * PP + y * WW + x) * CPAD;
    #pragma unroll
    for (int c = 0; c < CC; ++c) {
        float qv = lg[c] * inv;
        size_t o = ((size_t)n * CC + c) * PP + y * WW + x;
        d_q[o] = qv;
        split_half(qv, vh[c], vl[c]);
        if (write_out) outp[o] = qv;
    }
}

// ---------------- launch ----------------
extern "C" void kernel_launch(void* const* d_in, const int* in_sizes, int n_in,
                              void* d_out, int out_size) {
    const float* unary = (const float*)d_in[0];
    const float* ref   = (const float*)d_in[1];
    const float* gk    = (const float*)d_in[2];
    const float* kstd  = (const float*)d_in[3];
    float* out = (float*)d_out;

    feats_kernel<<<(NB * PP + 255) / 256, 256>>>(ref, kstd);
    g1d_kernel<<<1, 128>>>(gk);
    init_kernel<<<(NB * PP + 255) / 256, 256>>>(unary);
    buildK_kernel<<<dim3(PP / 128, PP / 32, NB), dim3(64, 4)>>>();

    for (int it = 0; it < 5; ++it) {
        vconv_kernel<<<(NB * CC * PP + 255) / 256, 256>>>();
        gemm_kernel<<<dim3(PP / BM, SPLITS, NB), 128>>>();
        hcombine_kernel<<<NB * HH, 64>>>(out, it == 4 ? 1 : 0);
    }
}